// round 3
// baseline (speedup 1.0000x reference)
#include <cuda_runtime.h>
#include <cstddef>

// GCNConv(16,8): out = D^-1/2 (A+I) D^-1/2 X W^T + b
// CSR-build + gather-reduce. Edge indices arrive as int32 (harness converts int64).
//   hs[n]  = dinv[n] * (x[n] @ W^T),  dinv[n] = rsqrt(deg[n]+1)
//   out[n] = dinv[n] * (hs[n] + sum_{e: dst[e]==n} hs[src[e]]) + b

#define MAXN 500000
#define MAXE 5000000
#define SCAN_B 1024

__device__ float g_hs[(size_t)MAXN * 8];   // 16 MB
__device__ float g_dinv[MAXN];
__device__ int   g_deg[MAXN];
__device__ int   g_off[MAXN];
__device__ int   g_cur[MAXN];
__device__ int   g_csr[MAXE];              // 20 MB
__device__ int   g_bsum[1024];
__device__ int   g_boff[1024];

// ---------------------------------------------------------------- zero degrees
__global__ void k_zero(int N) {
    int n = blockIdx.x * blockDim.x + threadIdx.x;
    if (n < N) g_deg[n] = 0;
}

// ---------------------------------------------------------------- degree count
__global__ void k_deg(const int* __restrict__ dst, int E, int N) {
    int e = blockIdx.x * blockDim.x + threadIdx.x;
    if (e < E) {
        int d = dst[e];
        if ((unsigned)d < (unsigned)N) atomicAdd(&g_deg[d], 1);
    }
}

// ---------------------------------------------------------------- scan pass 1: block sums
__global__ void k_scan1(int N) {
    __shared__ int s[SCAN_B];
    int t = threadIdx.x;
    int i = blockIdx.x * SCAN_B + t;
    s[t] = (i < N) ? g_deg[i] : 0;
    __syncthreads();
#pragma unroll
    for (int d = SCAN_B / 2; d > 0; d >>= 1) {
        if (t < d) s[t] += s[t + d];
        __syncthreads();
    }
    if (t == 0) g_bsum[blockIdx.x] = s[0];
}

// ---------------------------------------------------------------- scan pass 2: scan block sums (1 block)
__global__ void k_scan2(int nblocks) {
    __shared__ int sA[SCAN_B], sB[SCAN_B];
    int t = threadIdx.x;
    int* pin = sA;
    int* pout = sB;
    pin[t] = (t < nblocks) ? g_bsum[t] : 0;
    __syncthreads();
#pragma unroll
    for (int d = 1; d < SCAN_B; d <<= 1) {
        pout[t] = pin[t] + ((t >= d) ? pin[t - d] : 0);
        __syncthreads();
        int* tmp = pin; pin = pout; pout = tmp;
    }
    if (t < nblocks) g_boff[t] = t ? pin[t - 1] : 0;
}

// ---------------------------------------------------------------- scan pass 3: per-block exclusive scan + offset
__global__ void k_scan3(int N) {
    __shared__ int sA[SCAN_B], sB[SCAN_B];
    int t = threadIdx.x;
    int i = blockIdx.x * SCAN_B + t;
    int* pin = sA;
    int* pout = sB;
    pin[t] = (i < N) ? g_deg[i] : 0;
    __syncthreads();
#pragma unroll
    for (int d = 1; d < SCAN_B; d <<= 1) {
        pout[t] = pin[t] + ((t >= d) ? pin[t - d] : 0);
        __syncthreads();
        int* tmp = pin; pin = pout; pout = tmp;
    }
    if (i < N) {
        int excl = (t ? pin[t - 1] : 0) + g_boff[blockIdx.x];
        g_off[i] = excl;
        g_cur[i] = excl;
    }
}

// ---------------------------------------------------------------- CSR fill
__global__ void k_fill(const int* __restrict__ src,
                       const int* __restrict__ dst, int E, int N) {
    int e = blockIdx.x * blockDim.x + threadIdx.x;
    if (e >= E) return;
    int s = src[e];
    int d = dst[e];
    if ((unsigned)d >= (unsigned)N || (unsigned)s >= (unsigned)N) return;
    int pos = atomicAdd(&g_cur[d], 1);
    g_csr[pos] = s;
}

// ---------------------------------------------------------------- node transform: hs = dinv * (x @ W^T)
__global__ void k_node(const float* __restrict__ x, const float* __restrict__ W, int N) {
    __shared__ float sW[128];              // W is [8,16] row-major
    int t = threadIdx.x;
    if (t < 128) sW[t] = W[t];
    __syncthreads();

    int n = blockIdx.x * blockDim.x + t;
    if (n >= N) return;

    const float4* xp = (const float4*)(x + (size_t)n * 16);
    float4 v0 = xp[0], v1 = xp[1], v2 = xp[2], v3 = xp[3];
    float xr[16] = { v0.x, v0.y, v0.z, v0.w,  v1.x, v1.y, v1.z, v1.w,
                     v2.x, v2.y, v2.z, v2.w,  v3.x, v3.y, v3.z, v3.w };

    float dinv = rsqrtf((float)(g_deg[n] + 1));   // +1 self loop; always > 0
    g_dinv[n] = dinv;

    float h[8];
#pragma unroll
    for (int j = 0; j < 8; j++) {
        float s = 0.f;
#pragma unroll
        for (int i = 0; i < 16; i++) s = fmaf(xr[i], sW[j * 16 + i], s);
        h[j] = s * dinv;
    }

    float4* hsp = (float4*)(g_hs + (size_t)n * 8);
    hsp[0] = make_float4(h[0], h[1], h[2], h[3]);
    hsp[1] = make_float4(h[4], h[5], h[6], h[7]);
}

// ---------------------------------------------------------------- gather-reduce + epilogue
__global__ void k_gather(const float* __restrict__ bias, float* __restrict__ out, int N) {
    int n = blockIdx.x * blockDim.x + threadIdx.x;
    if (n >= N) return;

    const float4* hp = (const float4*)(g_hs + (size_t)n * 8);
    float4 a = hp[0], c = hp[1];           // self-loop message

    int off = g_off[n];
    int deg = g_deg[n];
    for (int k = 0; k < deg; k++) {
        int s = g_csr[off + k];
        const float4* sp = (const float4*)(g_hs + (size_t)s * 8);
        float4 u = sp[0], w = sp[1];
        a.x += u.x; a.y += u.y; a.z += u.z; a.w += u.w;
        c.x += w.x; c.y += w.y; c.z += w.z; c.w += w.w;
    }

    float dinv = g_dinv[n];
    const float4* bp = (const float4*)bias;
    float4 b0 = __ldg(bp), b1 = __ldg(bp + 1);

    float4 o0 = make_float4(fmaf(a.x, dinv, b0.x), fmaf(a.y, dinv, b0.y),
                            fmaf(a.z, dinv, b0.z), fmaf(a.w, dinv, b0.w));
    float4 o1 = make_float4(fmaf(c.x, dinv, b1.x), fmaf(c.y, dinv, b1.y),
                            fmaf(c.z, dinv, b1.z), fmaf(c.w, dinv, b1.w));

    float4* op = (float4*)(out + (size_t)n * 8);
    op[0] = o0;
    op[1] = o1;
}

// ---------------------------------------------------------------- launch
extern "C" void kernel_launch(void* const* d_in, const int* in_sizes, int n_in,
                              void* d_out, int out_size) {
    const float* x    = (const float*)d_in[0];   // [N,16] f32
    const int*   ei   = (const int*)d_in[1];     // [2,E]  int32 (converted from int64)
    const float* W    = (const float*)d_in[2];   // [8,16] f32
    const float* bias = (const float*)d_in[3];   // [8]    f32
    float*       out  = (float*)d_out;           // [N,8]  f32

    int N = in_sizes[0] / 16;
    int E = in_sizes[1] / 2;
    const int* src = ei;
    const int* dst = ei + E;

    const int T = 256;
    int gbN = (N + T - 1) / T;
    int gbE = (E + T - 1) / T;
    int nScanBlocks = (N + SCAN_B - 1) / SCAN_B;

    k_zero<<<gbN, T>>>(N);
    k_deg<<<gbE, T>>>(dst, E, N);
    k_scan1<<<nScanBlocks, SCAN_B>>>(N);
    k_scan2<<<1, SCAN_B>>>(nScanBlocks);
    k_scan3<<<nScanBlocks, SCAN_B>>>(N);
    k_node<<<gbN, T>>>(x, W, N);            // needs deg only
    k_fill<<<gbE, T>>>(src, dst, E, N);     // needs cursors
    k_gather<<<gbN, T>>>(bias, out, N);     // needs csr + hs
}

// round 4
// speedup vs baseline: 1.3359x; 1.3359x over previous
#include <cuda_runtime.h>
#include <cstddef>

// GCNConv(16,8): out = D^-1/2 (A+I) D^-1/2 X W^T + b
// CSR-build + channel-parallel gather-reduce (8 threads per node).
//   hs[n]  = dinv[n] * (x[n] @ W^T),  dinv[n] = rsqrt(deg[n]+1)
//   out[n] = dinv[n] * (hs[n] + sum_{e: dst[e]==n} hs[src[e]]) + b

#define MAXN 500000
#define MAXE 5000000
#define SCAN_B 1024

__device__ float g_hs[(size_t)MAXN * 8];   // 16 MB, L2-resident
__device__ float g_dinv[MAXN];
__device__ int   g_deg[MAXN];
__device__ int   g_off[MAXN];
__device__ int   g_cur[MAXN];
__device__ int   g_csr[MAXE];              // 20 MB
__device__ int   g_bsum[1024];
__device__ int   g_boff[1024];

// ---------------------------------------------------------------- zero degrees
__global__ void k_zero(int N) {
    int n = blockIdx.x * blockDim.x + threadIdx.x;
    if (n < N) g_deg[n] = 0;
}

// ---------------------------------------------------------------- degree count
__global__ void k_deg(const int* __restrict__ dst, int E, int N) {
    int e = blockIdx.x * blockDim.x + threadIdx.x;
    if (e < E) {
        int d = dst[e];
        if ((unsigned)d < (unsigned)N) atomicAdd(&g_deg[d], 1);
    }
}

// ---------------------------------------------------------------- scan pass 1: block sums
__global__ void k_scan1(int N) {
    __shared__ int s[SCAN_B];
    int t = threadIdx.x;
    int i = blockIdx.x * SCAN_B + t;
    s[t] = (i < N) ? g_deg[i] : 0;
    __syncthreads();
#pragma unroll
    for (int d = SCAN_B / 2; d > 0; d >>= 1) {
        if (t < d) s[t] += s[t + d];
        __syncthreads();
    }
    if (t == 0) g_bsum[blockIdx.x] = s[0];
}

// ---------------------------------------------------------------- scan pass 2: scan block sums (1 block)
__global__ void k_scan2(int nblocks) {
    __shared__ int sA[SCAN_B], sB[SCAN_B];
    int t = threadIdx.x;
    int* pin = sA;
    int* pout = sB;
    pin[t] = (t < nblocks) ? g_bsum[t] : 0;
    __syncthreads();
#pragma unroll
    for (int d = 1; d < SCAN_B; d <<= 1) {
        pout[t] = pin[t] + ((t >= d) ? pin[t - d] : 0);
        __syncthreads();
        int* tmp = pin; pin = pout; pout = tmp;
    }
    if (t < nblocks) g_boff[t] = t ? pin[t - 1] : 0;
}

// ---------------------------------------------------------------- scan pass 3: per-block exclusive scan + offset
__global__ void k_scan3(int N) {
    __shared__ int sA[SCAN_B], sB[SCAN_B];
    int t = threadIdx.x;
    int i = blockIdx.x * SCAN_B + t;
    int* pin = sA;
    int* pout = sB;
    pin[t] = (i < N) ? g_deg[i] : 0;
    __syncthreads();
#pragma unroll
    for (int d = 1; d < SCAN_B; d <<= 1) {
        pout[t] = pin[t] + ((t >= d) ? pin[t - d] : 0);
        __syncthreads();
        int* tmp = pin; pin = pout; pout = tmp;
    }
    if (i < N) {
        int excl = (t ? pin[t - 1] : 0) + g_boff[blockIdx.x];
        g_off[i] = excl;
        g_cur[i] = excl;
    }
}

// ---------------------------------------------------------------- CSR fill
__global__ void k_fill(const int* __restrict__ src,
                       const int* __restrict__ dst, int E, int N) {
    int e = blockIdx.x * blockDim.x + threadIdx.x;
    if (e >= E) return;
    int s = src[e];
    int d = dst[e];
    if ((unsigned)d >= (unsigned)N || (unsigned)s >= (unsigned)N) return;
    int pos = atomicAdd(&g_cur[d], 1);
    g_csr[pos] = s;
}

// ---------------------------------------------------------------- node transform: hs = dinv * (x @ W^T)
__global__ void k_node(const float* __restrict__ x, const float* __restrict__ W, int N) {
    __shared__ float sW[128];              // W is [8,16] row-major
    int t = threadIdx.x;
    if (t < 128) sW[t] = W[t];
    __syncthreads();

    int n = blockIdx.x * blockDim.x + t;
    if (n >= N) return;

    const float4* xp = (const float4*)(x + (size_t)n * 16);
    float4 v0 = xp[0], v1 = xp[1], v2 = xp[2], v3 = xp[3];
    float xr[16] = { v0.x, v0.y, v0.z, v0.w,  v1.x, v1.y, v1.z, v1.w,
                     v2.x, v2.y, v2.z, v2.w,  v3.x, v3.y, v3.z, v3.w };

    float dinv = rsqrtf((float)(g_deg[n] + 1));   // +1 self loop; always > 0
    g_dinv[n] = dinv;

    float h[8];
#pragma unroll
    for (int j = 0; j < 8; j++) {
        float s = 0.f;
#pragma unroll
        for (int i = 0; i < 16; i++) s = fmaf(xr[i], sW[j * 16 + i], s);
        h[j] = s * dinv;
    }

    float4* hsp = (float4*)(g_hs + (size_t)n * 8);
    hsp[0] = make_float4(h[0], h[1], h[2], h[3]);
    hsp[1] = make_float4(h[4], h[5], h[6], h[7]);
}

// ---------------------------------------------------------------- gather-reduce + epilogue
// 8 threads per node: thread (node, ch) owns one output channel.
// csr index load is an 8-way broadcast; hs loads coalesce to one 32B line/edge.
__global__ void k_gather(const float* __restrict__ bias, float* __restrict__ out, int N) {
    int t = threadIdx.x;
    int n = blockIdx.x * 32 + (t >> 3);
    int ch = t & 7;
    if (n >= N) return;

    float acc = g_hs[(size_t)n * 8 + ch];       // self-loop message
    int off = g_off[n];
    int deg = g_deg[n];
    const int* __restrict__ csr = g_csr + off;

#pragma unroll 4
    for (int k = 0; k < deg; k++) {
        int s = __ldg(&csr[k]);
        acc += __ldg(&g_hs[(size_t)s * 8 + ch]);
    }

    float dinv = g_dinv[n];
    float b = __ldg(&bias[ch]);
    out[(size_t)n * 8 + ch] = fmaf(acc, dinv, b);
}

// ---------------------------------------------------------------- launch
extern "C" void kernel_launch(void* const* d_in, const int* in_sizes, int n_in,
                              void* d_out, int out_size) {
    const float* x    = (const float*)d_in[0];   // [N,16] f32
    const int*   ei   = (const int*)d_in[1];     // [2,E]  int32 (converted from int64)
    const float* W    = (const float*)d_in[2];   // [8,16] f32
    const float* bias = (const float*)d_in[3];   // [8]    f32
    float*       out  = (float*)d_out;           // [N,8]  f32

    int N = in_sizes[0] / 16;
    int E = in_sizes[1] / 2;
    const int* src = ei;
    const int* dst = ei + E;

    const int T = 256;
    int gbN = (N + T - 1) / T;
    int gbE = (E + T - 1) / T;
    int nScanBlocks = (N + SCAN_B - 1) / SCAN_B;
    int gbG = (N + 31) / 32;                 // 32 nodes per 256-thread block

    k_zero<<<gbN, T>>>(N);
    k_deg<<<gbE, T>>>(dst, E, N);
    k_scan1<<<nScanBlocks, SCAN_B>>>(N);
    k_scan2<<<1, SCAN_B>>>(nScanBlocks);
    k_scan3<<<nScanBlocks, SCAN_B>>>(N);
    k_node<<<gbN, T>>>(x, W, N);            // needs deg only
    k_fill<<<gbE, T>>>(src, dst, E, N);     // needs cursors
    k_gather<<<gbG, T>>>(bias, out, N);     // needs csr + hs
}

// round 5
// speedup vs baseline: 1.7858x; 1.3368x over previous
#include <cuda_runtime.h>
#include <cstddef>

// GCNConv(16,8): out = D^-1/2 (A+I) D^-1/2 X W^T + b
// Atomic-scatter formulation (no CSR, no scans):
//   hs[n]  = dinv[n] * (x[n] @ W^T),  dinv[n] = rsqrt(deg[n]+1)
//   acc[n] = hs[n] + sum_{e: dst[e]==n} hs[src[e]]    (vector RED scatter)
//   out[n] = dinv[n] * acc[n] + b

#define MAXN 500000

__device__ float g_hs[(size_t)MAXN * 8];    // 16 MB, L2-resident
__device__ float g_acc[(size_t)MAXN * 8];   // 16 MB accumulator (own buffer!)
__device__ float g_dinv[MAXN];
__device__ int   g_deg[MAXN];

// ---------------------------------------------------------------- zero degrees
__global__ void k_zero(int N) {
    int n = blockIdx.x * blockDim.x + threadIdx.x;
    if (n < N) g_deg[n] = 0;
}

// ---------------------------------------------------------------- degree count (4 edges/thread)
__global__ void k_deg(const int* __restrict__ dst, int E, int N) {
    int i = blockIdx.x * blockDim.x + threadIdx.x;
    int e = i * 4;
    if (e + 3 < E) {
        int4 d4 = *(const int4*)(dst + e);
        if ((unsigned)d4.x < (unsigned)N) atomicAdd(&g_deg[d4.x], 1);
        if ((unsigned)d4.y < (unsigned)N) atomicAdd(&g_deg[d4.y], 1);
        if ((unsigned)d4.z < (unsigned)N) atomicAdd(&g_deg[d4.z], 1);
        if ((unsigned)d4.w < (unsigned)N) atomicAdd(&g_deg[d4.w], 1);
    } else {
        for (; e < E; e++) {
            int d = dst[e];
            if ((unsigned)d < (unsigned)N) atomicAdd(&g_deg[d], 1);
        }
    }
}

// ---------------------------------------------------------------- node transform
// hs = dinv * (x @ W^T); acc initialized to hs (self-loop message).
__global__ void k_node(const float* __restrict__ x, const float* __restrict__ W, int N) {
    __shared__ float sW[128];               // W is [8,16] row-major
    int t = threadIdx.x;
    if (t < 128) sW[t] = W[t];
    __syncthreads();

    int n = blockIdx.x * blockDim.x + t;
    if (n >= N) return;

    const float4* xp = (const float4*)(x + (size_t)n * 16);
    float4 v0 = xp[0], v1 = xp[1], v2 = xp[2], v3 = xp[3];
    float xr[16] = { v0.x, v0.y, v0.z, v0.w,  v1.x, v1.y, v1.z, v1.w,
                     v2.x, v2.y, v2.z, v2.w,  v3.x, v3.y, v3.z, v3.w };

    float dinv = rsqrtf((float)(g_deg[n] + 1));   // +1 self loop; always > 0
    g_dinv[n] = dinv;

    float h[8];
#pragma unroll
    for (int j = 0; j < 8; j++) {
        float s = 0.f;
#pragma unroll
        for (int i = 0; i < 16; i++) s = fmaf(xr[i], sW[j * 16 + i], s);
        h[j] = s * dinv;
    }

    float4 a = make_float4(h[0], h[1], h[2], h[3]);
    float4 c = make_float4(h[4], h[5], h[6], h[7]);

    float4* hsp = (float4*)(g_hs + (size_t)n * 8);
    hsp[0] = a; hsp[1] = c;
    float4* ap = (float4*)(g_acc + (size_t)n * 8);
    ap[0] = a; ap[1] = c;                   // accumulator init = self-loop msg
}

// ---------------------------------------------------------------- edge scatter
// acc[dst] += hs[src], 2 edges per thread, no-return vector reductions.
__global__ void k_scatter(const int* __restrict__ src,
                          const int* __restrict__ dst, int E, int N) {
    int i = blockIdx.x * blockDim.x + threadIdx.x;
    int e = i * 2;
    if (e >= E) return;

    int ecnt = (e + 1 < E) ? 2 : 1;
    int2 s2, d2;
    if (ecnt == 2) {
        s2 = *(const int2*)(src + e);
        d2 = *(const int2*)(dst + e);
    } else {
        s2.x = src[e]; d2.x = dst[e];
        s2.y = 0;      d2.y = -1;           // will fail bounds check
    }

#pragma unroll
    for (int j = 0; j < 2; j++) {
        int s = j ? s2.y : s2.x;
        int d = j ? d2.y : d2.x;
        if ((unsigned)s >= (unsigned)N || (unsigned)d >= (unsigned)N) continue;

        const float4* hp = (const float4*)(g_hs + (size_t)s * 8);
        float4 a = hp[0], c = hp[1];

        float* dp = g_acc + (size_t)d * 8;
        asm volatile("red.global.add.v4.f32 [%0], {%1,%2,%3,%4};"
                     :: "l"(dp), "f"(a.x), "f"(a.y), "f"(a.z), "f"(a.w) : "memory");
        asm volatile("red.global.add.v4.f32 [%0], {%1,%2,%3,%4};"
                     :: "l"(dp + 4), "f"(c.x), "f"(c.y), "f"(c.z), "f"(c.w) : "memory");
    }
}

// ---------------------------------------------------------------- finalize
__global__ void k_final(const float* __restrict__ bias, float* __restrict__ out, int N) {
    int n = blockIdx.x * blockDim.x + threadIdx.x;
    if (n >= N) return;

    float dinv = g_dinv[n];
    const float4* bp = (const float4*)bias;
    float4 b0 = __ldg(bp), b1 = __ldg(bp + 1);

    const float4* ap = (const float4*)(g_acc + (size_t)n * 8);
    float4 a = ap[0], c = ap[1];

    float4 o0 = make_float4(fmaf(a.x, dinv, b0.x), fmaf(a.y, dinv, b0.y),
                            fmaf(a.z, dinv, b0.z), fmaf(a.w, dinv, b0.w));
    float4 o1 = make_float4(fmaf(c.x, dinv, b1.x), fmaf(c.y, dinv, b1.y),
                            fmaf(c.z, dinv, b1.z), fmaf(c.w, dinv, b1.w));

    float4* op = (float4*)(out + (size_t)n * 8);
    op[0] = o0;
    op[1] = o1;
}

// ---------------------------------------------------------------- launch
extern "C" void kernel_launch(void* const* d_in, const int* in_sizes, int n_in,
                              void* d_out, int out_size) {
    const float* x    = (const float*)d_in[0];   // [N,16] f32
    const int*   ei   = (const int*)d_in[1];     // [2,E]  int32 (converted from int64)
    const float* W    = (const float*)d_in[2];   // [8,16] f32
    const float* bias = (const float*)d_in[3];   // [8]    f32
    float*       out  = (float*)d_out;           // [N,8]  f32

    int N = in_sizes[0] / 16;
    int E = in_sizes[1] / 2;
    const int* src = ei;
    const int* dst = ei + E;

    const int T = 256;
    int gbN  = (N + T - 1) / T;
    int gbE4 = (E / 4 + T - 1) / T + 1;      // 4 edges/thread (+1 block for tail)
    int gbE2 = ((E + 1) / 2 + T - 1) / T;    // 2 edges/thread

    k_zero<<<gbN, T>>>(N);
    k_deg<<<gbE4, T>>>(dst, E, N);
    k_node<<<gbN, T>>>(x, W, N);
    k_scatter<<<gbE2, T>>>(src, dst, E, N);
    k_final<<<gbN, T>>>(bias, out, N);
}